// round 16
// baseline (speedup 1.0000x reference)
#include <cuda_runtime.h>
#include <mma.h>

using namespace nvcuda;

#define HID  128
#define NIN  64
#define NOUT 64
#define NB   256
#define NS   4096

// xp[b][s][j] = x@Wx + bh + bx (bias folded), float. 512 MB.
__device__ float g_xp[NB][NS][HID];
// hs[b][s][j], float. 512 MB.
__device__ float g_hs[NB][NS][HID];
// tf32 hi/lo splits of the GEMM weights (prep kernel).
__device__ float g_wx_hi[NIN][HID], g_wx_lo[NIN][HID];
__device__ float g_wy_hi[HID][NOUT], g_wy_lo[HID][NOUT];

// ---------------------------------------------------------------------------
// Kernel 0: split Wx / Wy into tf32 hi/lo pairs.
// ---------------------------------------------------------------------------
__global__ void __launch_bounds__(256) prep_split(
    const float* __restrict__ Wx, const float* __restrict__ Wy)
{
    int t = blockIdx.x * 256 + threadIdx.x;
    int n = 256 * gridDim.x;
    float* wxh = &g_wx_hi[0][0]; float* wxl = &g_wx_lo[0][0];
    float* wyh = &g_wy_hi[0][0]; float* wyl = &g_wy_lo[0][0];
    for (int i = t; i < NIN * HID; i += n) {
        float v = Wx[i];
        float h = wmma::__float_to_tf32(v);
        wxh[i] = h;
        wxl[i] = wmma::__float_to_tf32(v - h);
    }
    for (int i = t; i < HID * NOUT; i += n) {
        float v = Wy[i];
        float h = wmma::__float_to_tf32(v);
        wyh[i] = h;
        wyl[i] = wmma::__float_to_tf32(v - h);
    }
}

// ---------------------------------------------------------------------------
// Kernel 1 (tensor): xp = x@Wx + bh + bx for 32-step tiles.
// 128 thr / 4 warps. A = x tile (32x64) split hi/lo in smem; B = g_wx_hi/lo
// from global. 3-term tf32 split mma (m16n16k8). Bias added in the STG pass.
// ---------------------------------------------------------------------------
__global__ void __launch_bounds__(128) xp_tensor(
    const float* __restrict__ x,
    const float* __restrict__ bh, const float* __restrict__ bx, int s_base)
{
    __shared__ __align__(16) float a_hi[32][72], a_lo[32][72];
    __shared__ __align__(16) float stage[32][128];

    const int t = threadIdx.x;
    const int w = t >> 5;
    const int b  = blockIdx.y;
    const int s0 = s_base + blockIdx.x * 32;

    // Load + split x tile: 32 s x 64 i = 2048 elements, 16/thread.
#pragma unroll
    for (int q = 0; q < 16; q++) {
        int idx = t + q * 128;
        int s = idx >> 6, i = idx & 63;
        float v = x[((long long)b * NS + s0 + s) * NIN + i];
        float h = wmma::__float_to_tf32(v);
        a_hi[s][i] = h;
        a_lo[s][i] = wmma::__float_to_tf32(v - h);
    }
    __syncthreads();

    // Warp w covers n-tiles {2w, 2w+1}, m-tiles {0,1}. K = 64 -> 8 k-steps.
#pragma unroll
    for (int p = 0; p < 4; p++) {
        int mt = p & 1;
        int nt = w * 2 + (p >> 1);
        wmma::fragment<wmma::accumulator, 16, 16, 8, float> acc;
        wmma::fill_fragment(acc, 0.f);
#pragma unroll
        for (int kt = 0; kt < 8; kt++) {
            wmma::fragment<wmma::matrix_a, 16, 16, 8, wmma::precision::tf32, wmma::row_major> ah, al;
            wmma::fragment<wmma::matrix_b, 16, 16, 8, wmma::precision::tf32, wmma::row_major> bhf, blf;
            wmma::load_matrix_sync(ah, &a_hi[mt * 16][kt * 8], 72);
            wmma::load_matrix_sync(al, &a_lo[mt * 16][kt * 8], 72);
            wmma::load_matrix_sync(bhf, &g_wx_hi[kt * 8][nt * 16], HID);
            wmma::load_matrix_sync(blf, &g_wx_lo[kt * 8][nt * 16], HID);
            wmma::mma_sync(acc, ah, bhf, acc);
            wmma::mma_sync(acc, ah, blf, acc);
            wmma::mma_sync(acc, al, bhf, acc);
        }
        wmma::store_matrix_sync(&stage[mt * 16][nt * 16], acc, 128, wmma::mem_row_major);
    }
    __syncthreads();

    // Bias add + coalesced STG: 4096 elements, 32/thread.
#pragma unroll
    for (int q = 0; q < 32; q++) {
        int idx = t + q * 128;
        int s = idx >> 7, j = idx & 127;
        g_xp[b][s0 + s][j] = stage[s][j] + bh[j] + bx[j];
    }
}

// ---------------------------------------------------------------------------
// Kernel 2: recurrence chunk [s0,s1), s0/s1 % 4 == 0.  (R13, unchanged)
// ---------------------------------------------------------------------------
__global__ void __launch_bounds__(256, 1) rnn_rec_chunk(
    const float* __restrict__ Wh, int s0, int s1)
{
    __shared__ __align__(16) float hbufF[2][2][HID];     // [grp][buf][j]
    __shared__ __align__(16) float xsr[2][2][4][HID];    // [grp][slot][st][j]

    const int tid = threadIdx.x;
    const int g   = tid >> 7;
    const int u   = tid & 127;
    const int b   = blockIdx.x * 2 + g;
    const int bar = g + 1;

    float whc[128];
#pragma unroll
    for (int k = 0; k < 128; k++)
        whc[k] = Wh[k * HID + u];

    const int st_ld = u >> 5;
    const int j4    = (u & 31) * 4;

    const int B0 = s0 >> 2, B1 = s1 >> 2;

    hbufF[g][0][u] = (s0 == 0) ? 0.f : g_hs[b][s0 - 1][u];
    *(float4*)&xsr[g][B0 & 1][st_ld][j4] =
        *(const float4*)&g_xp[b][4 * B0 + st_ld][j4];
    float4 xr = make_float4(0.f, 0.f, 0.f, 0.f);
    if (4 * (B0 + 1) < NS)
        xr = *(const float4*)&g_xp[b][4 * (B0 + 1) + st_ld][j4];
    asm volatile("bar.sync %0, 128;" :: "r"(bar) : "memory");

    for (int bc = B0; bc < B1; bc++) {
        if (4 * (bc + 1) < NS)
            *(float4*)&xsr[g][(bc + 1) & 1][st_ld][j4] = xr;
        if (4 * (bc + 2) < NS)
            xr = *(const float4*)&g_xp[b][4 * (bc + 2) + st_ld][j4];

#pragma unroll
        for (int st = 0; st < 4; st++) {
            const int cur = st & 1, nxt = cur ^ 1;

            float a0 = xsr[g][bc & 1][st][u];
            float a1 = 0.f, a2 = 0.f, a3 = 0.f;
            const float* hb = hbufF[g][cur];
#pragma unroll
            for (int m = 0; m < 128; m += 4) {
                float4 hv = *(const float4*)(hb + m);
                a0 = fmaf(whc[m],     hv.x, a0);
                a1 = fmaf(whc[m + 1], hv.y, a1);
                a2 = fmaf(whc[m + 2], hv.z, a2);
                a3 = fmaf(whc[m + 3], hv.w, a3);
            }
            float h = fmaxf((a0 + a1) + (a2 + a3), 0.f);
            hbufF[g][nxt][u] = h;
            g_hs[b][4 * bc + st][u] = h;
            asm volatile("bar.sync %0, 128;" :: "r"(bar) : "memory");
        }
    }
}

// ---------------------------------------------------------------------------
// Kernel 3 (tensor): out[b][s][o] = hs@Wy + by for 32-step tiles.
// 128 thr / 4 warps. A = hs tile (32x128) split hi/lo in smem; B = g_wy_hi/lo
// from global. 3-term tf32 split mma.
// ---------------------------------------------------------------------------
__global__ void __launch_bounds__(128) out_tensor(
    const float* __restrict__ by, float* __restrict__ out, int s_base)
{
    __shared__ __align__(16) float a_hi[32][136], a_lo[32][136];
    __shared__ __align__(16) float stage[32][64];

    const int t = threadIdx.x;
    const int w = t >> 5;
    const int b  = blockIdx.y;
    const int s0 = s_base + blockIdx.x * 32;

    // Load + split hs tile: 32 s x 128 j = 4096 elements, 32/thread.
#pragma unroll
    for (int q = 0; q < 32; q++) {
        int idx = t + q * 128;
        int s = idx >> 7, j = idx & 127;
        float v = g_hs[b][s0 + s][j];
        float h = wmma::__float_to_tf32(v);
        a_hi[s][j] = h;
        a_lo[s][j] = wmma::__float_to_tf32(v - h);
    }
    __syncthreads();

    // Warp w covers n-tile w, m-tiles {0,1}. K = 128 -> 16 k-steps.
#pragma unroll
    for (int mt = 0; mt < 2; mt++) {
        wmma::fragment<wmma::accumulator, 16, 16, 8, float> acc;
        wmma::fill_fragment(acc, 0.f);
#pragma unroll
        for (int kt = 0; kt < 16; kt++) {
            wmma::fragment<wmma::matrix_a, 16, 16, 8, wmma::precision::tf32, wmma::row_major> ah, al;
            wmma::fragment<wmma::matrix_b, 16, 16, 8, wmma::precision::tf32, wmma::row_major> bhf, blf;
            wmma::load_matrix_sync(ah, &a_hi[mt * 16][kt * 8], 136);
            wmma::load_matrix_sync(al, &a_lo[mt * 16][kt * 8], 136);
            wmma::load_matrix_sync(bhf, &g_wy_hi[kt * 8][w * 16], NOUT);
            wmma::load_matrix_sync(blf, &g_wy_lo[kt * 8][w * 16], NOUT);
            wmma::mma_sync(acc, ah, bhf, acc);
            wmma::mma_sync(acc, ah, blf, acc);
            wmma::mma_sync(acc, al, bhf, acc);
        }
        wmma::store_matrix_sync(&stage[mt * 16][w * 16], acc, 64, wmma::mem_row_major);
    }
    __syncthreads();

    // Bias add + coalesced STG: 2048 elements, 16/thread.
#pragma unroll
    for (int q = 0; q < 16; q++) {
        int idx = t + q * 128;
        int s = idx >> 6, o = idx & 63;
        out[((long long)b * NS + s0 + s) * NOUT + o] = stage[s][o] + by[o];
    }
}

// ---------------------------------------------------------------------------
// 4-chunk two-stream pipeline (chunks of 1024 steps, 32 tiles each):
//   main: prep | xp0 | rec0 | rec1 | rec2 | rec3 | out3
//   s1:                xp1, xp2, xp3, out0, out1, out2   (tensor pipe)
// Deps: rec_k <- xp_k; out_k <- rec_k; out3 <- out0..2.
// ---------------------------------------------------------------------------
extern "C" void kernel_launch(void* const* d_in, const int* in_sizes, int n_in,
                              void* d_out, int out_size)
{
    const float* x  = (const float*)d_in[0];
    const float* Wh = (const float*)d_in[1];
    const float* bh = (const float*)d_in[2];
    const float* Wx = (const float*)d_in[3];
    const float* bx = (const float*)d_in[4];
    const float* Wy = (const float*)d_in[5];
    const float* by = (const float*)d_in[6];
    float* out = (float*)d_out;

    static cudaStream_t s1 = nullptr;
    static cudaEvent_t ev0, evX1, evX2, evX3, evR0, evR1, evR2, evOut;
    if (s1 == nullptr) {
        cudaStreamCreateWithFlags(&s1, cudaStreamNonBlocking);
        cudaEventCreateWithFlags(&ev0,   cudaEventDisableTiming);
        cudaEventCreateWithFlags(&evX1,  cudaEventDisableTiming);
        cudaEventCreateWithFlags(&evX2,  cudaEventDisableTiming);
        cudaEventCreateWithFlags(&evX3,  cudaEventDisableTiming);
        cudaEventCreateWithFlags(&evR0,  cudaEventDisableTiming);
        cudaEventCreateWithFlags(&evR1,  cudaEventDisableTiming);
        cudaEventCreateWithFlags(&evR2,  cudaEventDisableTiming);
        cudaEventCreateWithFlags(&evOut, cudaEventDisableTiming);
    }

    // prep + xp0 serial on main
    prep_split<<<32, 256>>>(Wx, Wy);
    xp_tensor<<<dim3(32, NB), 128>>>(x, bh, bx, 0);
    cudaEventRecord(ev0, 0);

    // xp1..xp3 on s1 (tensor pipe, overlaps rec chain)
    cudaStreamWaitEvent(s1, ev0, 0);
    xp_tensor<<<dim3(32, NB), 128, 0, s1>>>(x, bh, bx, 1024);
    cudaEventRecord(evX1, s1);
    xp_tensor<<<dim3(32, NB), 128, 0, s1>>>(x, bh, bx, 2048);
    cudaEventRecord(evX2, s1);
    xp_tensor<<<dim3(32, NB), 128, 0, s1>>>(x, bh, bx, 3072);
    cudaEventRecord(evX3, s1);

    // rec chain on main, gated by xp events
    rnn_rec_chunk<<<NB / 2, 256>>>(Wh, 0, 1024);
    cudaEventRecord(evR0, 0);
    cudaStreamWaitEvent(0, evX1, 0);
    rnn_rec_chunk<<<NB / 2, 256>>>(Wh, 1024, 2048);
    cudaEventRecord(evR1, 0);
    cudaStreamWaitEvent(0, evX2, 0);
    rnn_rec_chunk<<<NB / 2, 256>>>(Wh, 2048, 3072);
    cudaEventRecord(evR2, 0);
    cudaStreamWaitEvent(0, evX3, 0);
    rnn_rec_chunk<<<NB / 2, 256>>>(Wh, 3072, 4096);

    // out0..out2 on s1, gated by rec events
    cudaStreamWaitEvent(s1, evR0, 0);
    out_tensor<<<dim3(32, NB), 128, 0, s1>>>(by, out, 0);
    cudaStreamWaitEvent(s1, evR1, 0);
    out_tensor<<<dim3(32, NB), 128, 0, s1>>>(by, out, 1024);
    cudaStreamWaitEvent(s1, evR2, 0);
    out_tensor<<<dim3(32, NB), 128, 0, s1>>>(by, out, 2048);
    cudaEventRecord(evOut, s1);

    // join + out3 on main
    cudaStreamWaitEvent(0, evOut, 0);
    out_tensor<<<dim3(32, NB), 128>>>(by, out, 3072);
}

// round 17
// speedup vs baseline: 1.0462x; 1.0462x over previous
#include <cuda_runtime.h>
#include <mma.h>

using namespace nvcuda;

#define HID  128
#define NIN  64
#define NOUT 64
#define NB   256
#define NS   4096

// xp[b][s][j] = x@Wx (NO bias; rec adds it), float. 512 MB.
__device__ float g_xp[NB][NS][HID];
// hs[b][s][j], float. 512 MB.
__device__ float g_hs[NB][NS][HID];
// tf32 hi/lo splits of the GEMM weights (prep kernel).
__device__ float g_wx_hi[NIN][HID], g_wx_lo[NIN][HID];
__device__ float g_wy_hi[HID][NOUT], g_wy_lo[HID][NOUT];

typedef wmma::fragment<wmma::matrix_a, 16, 16, 8, wmma::precision::tf32, wmma::row_major> FragA;
typedef wmma::fragment<wmma::matrix_b, 16, 16, 8, wmma::precision::tf32, wmma::row_major> FragB;
typedef wmma::fragment<wmma::accumulator, 16, 16, 8, float> FragC;

// ---------------------------------------------------------------------------
// Kernel 0: split Wx / Wy into tf32 hi/lo pairs.
// ---------------------------------------------------------------------------
__global__ void __launch_bounds__(256) prep_split(
    const float* __restrict__ Wx, const float* __restrict__ Wy)
{
    int t = blockIdx.x * 256 + threadIdx.x;
    int n = 256 * gridDim.x;
    float* wxh = &g_wx_hi[0][0]; float* wxl = &g_wx_lo[0][0];
    float* wyh = &g_wy_hi[0][0]; float* wyl = &g_wy_lo[0][0];
    for (int i = t; i < NIN * HID; i += n) {
        float v = Wx[i];
        float h = wmma::__float_to_tf32(v);
        wxh[i] = h;
        wxl[i] = wmma::__float_to_tf32(v - h);
    }
    for (int i = t; i < HID * NOUT; i += n) {
        float v = Wy[i];
        float h = wmma::__float_to_tf32(v);
        wyh[i] = h;
        wyl[i] = wmma::__float_to_tf32(v - h);
    }
}

// ---------------------------------------------------------------------------
// Kernel 1 (tensor v2): g_xp = x@Wx for 64-step tiles. 256 thr / 8 warps.
// Warp w owns n-slice [16w,16w+16). B frags (8 kt x hi/lo = 64 regs) loaded
// ONCE per warp. A (64x64) split hi/lo into smem once. 4 m-tiles; accs stored
// straight to g_xp via store_matrix_sync (ldm=128). No bias (rec adds it).
// ---------------------------------------------------------------------------
__global__ void __launch_bounds__(256) xp_tensor(
    const float* __restrict__ x, int s_base)
{
    __shared__ __align__(16) float a_hi[64][72], a_lo[64][72];

    const int t = threadIdx.x;
    const int w = t >> 5;
    const int b  = blockIdx.y;
    const int s0 = s_base + blockIdx.x * 64;

    // B fragments: resident for the whole kernel.
    FragB bh8[8], bl8[8];
#pragma unroll
    for (int kt = 0; kt < 8; kt++) {
        wmma::load_matrix_sync(bh8[kt], &g_wx_hi[kt * 8][w * 16], HID);
        wmma::load_matrix_sync(bl8[kt], &g_wx_lo[kt * 8][w * 16], HID);
    }

    // Load + split A tile: 64 s x 64 i = 1024 float4, 4 per thread, coalesced.
#pragma unroll
    for (int q = 0; q < 4; q++) {
        int idx4 = t + q * 256;
        int s  = idx4 >> 4;
        int i4 = (idx4 & 15) * 4;
        float4 v = *(const float4*)&x[((long long)b * NS + s0 + s) * NIN + i4];
        float h0 = wmma::__float_to_tf32(v.x);
        float h1 = wmma::__float_to_tf32(v.y);
        float h2 = wmma::__float_to_tf32(v.z);
        float h3 = wmma::__float_to_tf32(v.w);
        a_hi[s][i4]     = h0;  a_lo[s][i4]     = wmma::__float_to_tf32(v.x - h0);
        a_hi[s][i4 + 1] = h1;  a_lo[s][i4 + 1] = wmma::__float_to_tf32(v.y - h1);
        a_hi[s][i4 + 2] = h2;  a_lo[s][i4 + 2] = wmma::__float_to_tf32(v.z - h2);
        a_hi[s][i4 + 3] = h3;  a_lo[s][i4 + 3] = wmma::__float_to_tf32(v.w - h3);
    }
    __syncthreads();

#pragma unroll
    for (int mt = 0; mt < 4; mt++) {
        FragC acc;
        wmma::fill_fragment(acc, 0.f);
#pragma unroll
        for (int kt = 0; kt < 8; kt++) {
            FragA ah, al;
            wmma::load_matrix_sync(ah, &a_hi[mt * 16][kt * 8], 72);
            wmma::load_matrix_sync(al, &a_lo[mt * 16][kt * 8], 72);
            wmma::mma_sync(acc, ah, bh8[kt], acc);
            wmma::mma_sync(acc, ah, bl8[kt], acc);
            wmma::mma_sync(acc, al, bh8[kt], acc);
        }
        wmma::store_matrix_sync(&g_xp[b][s0 + mt * 16][w * 16], acc, HID,
                                wmma::mem_row_major);
    }
}

// ---------------------------------------------------------------------------
// Kernel 2: recurrence chunk [s0,s1).  (R13 + bias fold: xp has no bias.)
// ---------------------------------------------------------------------------
__global__ void __launch_bounds__(256, 1) rnn_rec_chunk(
    const float* __restrict__ Wh, const float* __restrict__ bh,
    const float* __restrict__ bx, int s0, int s1)
{
    __shared__ __align__(16) float hbufF[2][2][HID];     // [grp][buf][j]
    __shared__ __align__(16) float xsr[2][2][4][HID];    // [grp][slot][st][j]

    const int tid = threadIdx.x;
    const int g   = tid >> 7;
    const int u   = tid & 127;
    const int b   = blockIdx.x * 2 + g;
    const int bar = g + 1;

    float whc[128];
#pragma unroll
    for (int k = 0; k < 128; k++)
        whc[k] = Wh[k * HID + u];
    const float bsum = bh[u] + bx[u];

    const int st_ld = u >> 5;
    const int j4    = (u & 31) * 4;

    const int B0 = s0 >> 2, B1 = s1 >> 2;

    hbufF[g][0][u] = (s0 == 0) ? 0.f : g_hs[b][s0 - 1][u];
    *(float4*)&xsr[g][B0 & 1][st_ld][j4] =
        *(const float4*)&g_xp[b][4 * B0 + st_ld][j4];
    float4 xr = make_float4(0.f, 0.f, 0.f, 0.f);
    if (4 * (B0 + 1) < NS)
        xr = *(const float4*)&g_xp[b][4 * (B0 + 1) + st_ld][j4];
    asm volatile("bar.sync %0, 128;" :: "r"(bar) : "memory");

    for (int bc = B0; bc < B1; bc++) {
        if (4 * (bc + 1) < NS)
            *(float4*)&xsr[g][(bc + 1) & 1][st_ld][j4] = xr;
        if (4 * (bc + 2) < NS)
            xr = *(const float4*)&g_xp[b][4 * (bc + 2) + st_ld][j4];

#pragma unroll
        for (int st = 0; st < 4; st++) {
            const int cur = st & 1, nxt = cur ^ 1;

            float a0 = xsr[g][bc & 1][st][u] + bsum;
            float a1 = 0.f, a2 = 0.f, a3 = 0.f;
            const float* hb = hbufF[g][cur];
#pragma unroll
            for (int m = 0; m < 128; m += 4) {
                float4 hv = *(const float4*)(hb + m);
                a0 = fmaf(whc[m],     hv.x, a0);
                a1 = fmaf(whc[m + 1], hv.y, a1);
                a2 = fmaf(whc[m + 2], hv.z, a2);
                a3 = fmaf(whc[m + 3], hv.w, a3);
            }
            float h = fmaxf((a0 + a1) + (a2 + a3), 0.f);
            hbufF[g][nxt][u] = h;
            g_hs[b][4 * bc + st][u] = h;
            asm volatile("bar.sync %0, 128;" :: "r"(bar) : "memory");
        }
    }
}

// ---------------------------------------------------------------------------
// Kernel 3 (tensor v2): out = hs@Wy + by for 32-step tiles. 256 thr / 8 warps.
// Warp w = (kh = w>>2, nsl = w&3): k-half [64kh,64kh+64), n-slice
// [16nsl,16nsl+16). B frags (8 kt x hi/lo = 64 regs) resident. A (32x128)
// split hi/lo into a smem pool; after mma the pool is REUSED as the k-half
// reduction stage (2 x 32 x 72). Final pass: halves + bias, coalesced STG.
// ---------------------------------------------------------------------------
__global__ void __launch_bounds__(256) out_tensor(
    const float* __restrict__ by, float* __restrict__ out, int s_base)
{
    __shared__ __align__(16) float pool[2 * 32 * 136];   // 34.8 KB
    float* a_hi = pool;                   // [32][136]
    float* a_lo = pool + 32 * 136;        // [32][136]

    const int t  = threadIdx.x;
    const int w  = t >> 5;
    const int kh = w >> 2;
    const int nsl = w & 3;
    const int b  = blockIdx.y;
    const int s0 = s_base + blockIdx.x * 32;

    FragB bh8[8], bl8[8];
#pragma unroll
    for (int kt = 0; kt < 8; kt++) {
        wmma::load_matrix_sync(bh8[kt], &g_wy_hi[kh * 64 + kt * 8][nsl * 16], NOUT);
        wmma::load_matrix_sync(bl8[kt], &g_wy_lo[kh * 64 + kt * 8][nsl * 16], NOUT);
    }

    // Load + split A tile: 32 s x 128 j = 1024 float4, 4 per thread.
#pragma unroll
    for (int q = 0; q < 4; q++) {
        int idx4 = t + q * 256;
        int s  = idx4 >> 5;
        int j4 = (idx4 & 31) * 4;
        float4 v = *(const float4*)&g_hs[b][s0 + s][j4];
        float h0 = wmma::__float_to_tf32(v.x);
        float h1 = wmma::__float_to_tf32(v.y);
        float h2 = wmma::__float_to_tf32(v.z);
        float h3 = wmma::__float_to_tf32(v.w);
        a_hi[s * 136 + j4]     = h0;  a_lo[s * 136 + j4]     = wmma::__float_to_tf32(v.x - h0);
        a_hi[s * 136 + j4 + 1] = h1;  a_lo[s * 136 + j4 + 1] = wmma::__float_to_tf32(v.y - h1);
        a_hi[s * 136 + j4 + 2] = h2;  a_lo[s * 136 + j4 + 2] = wmma::__float_to_tf32(v.z - h2);
        a_hi[s * 136 + j4 + 3] = h3;  a_lo[s * 136 + j4 + 3] = wmma::__float_to_tf32(v.w - h3);
    }
    __syncthreads();

    // All mma with accs in registers (A smem is dead after this).
    FragC acc0, acc1;
    wmma::fill_fragment(acc0, 0.f);
    wmma::fill_fragment(acc1, 0.f);
#pragma unroll
    for (int kt = 0; kt < 8; kt++) {
        FragA ah, al;
        wmma::load_matrix_sync(ah, &a_hi[0 * 16 * 136 + kh * 64 + kt * 8], 136);
        wmma::load_matrix_sync(al, &a_lo[0 * 16 * 136 + kh * 64 + kt * 8], 136);
        wmma::mma_sync(acc0, ah, bh8[kt], acc0);
        wmma::mma_sync(acc0, ah, bl8[kt], acc0);
        wmma::mma_sync(acc0, al, bh8[kt], acc0);
        wmma::load_matrix_sync(ah, &a_hi[16 * 136 + kh * 64 + kt * 8], 136);
        wmma::load_matrix_sync(al, &a_lo[16 * 136 + kh * 64 + kt * 8], 136);
        wmma::mma_sync(acc1, ah, bh8[kt], acc1);
        wmma::mma_sync(acc1, ah, bl8[kt], acc1);
        wmma::mma_sync(acc1, al, bh8[kt], acc1);
    }
    __syncthreads();

    // Reuse pool as stage[2][32][72].
    float* stg = pool;
    wmma::store_matrix_sync(stg + kh * (32 * 72) + 0 * 16 * 72 + nsl * 16,
                            acc0, 72, wmma::mem_row_major);
    wmma::store_matrix_sync(stg + kh * (32 * 72) + 16 * 72 + nsl * 16,
                            acc1, 72, wmma::mem_row_major);
    __syncthreads();

    // Final: halves + bias, 32 s x 64 o = 2048, 8 per thread, coalesced.
#pragma unroll
    for (int q = 0; q < 8; q++) {
        int idx = t + q * 256;
        int s = idx >> 6, o = idx & 63;
        float r = stg[s * 72 + o] + stg[32 * 72 + s * 72 + o] + by[o];
        out[((long long)b * NS + s0 + s) * NOUT + o] = r;
    }
}

// ---------------------------------------------------------------------------
// 4-chunk two-stream pipeline (1024 steps/chunk):
//   main: prep | xp0 | rec0 | rec1 | rec2 | rec3 | out3
//   s1:                xp1, xp2, xp3, out0, out1, out2
// ---------------------------------------------------------------------------
extern "C" void kernel_launch(void* const* d_in, const int* in_sizes, int n_in,
                              void* d_out, int out_size)
{
    const float* x  = (const float*)d_in[0];
    const float* Wh = (const float*)d_in[1];
    const float* bh = (const float*)d_in[2];
    const float* Wx = (const float*)d_in[3];
    const float* bx = (const float*)d_in[4];
    const float* Wy = (const float*)d_in[5];
    const float* by = (const float*)d_in[6];
    float* out = (float*)d_out;

    static cudaStream_t s1 = nullptr;
    static cudaEvent_t ev0, evX1, evX2, evX3, evR0, evR1, evR2, evOut;
    if (s1 == nullptr) {
        cudaStreamCreateWithFlags(&s1, cudaStreamNonBlocking);
        cudaEventCreateWithFlags(&ev0,   cudaEventDisableTiming);
        cudaEventCreateWithFlags(&evX1,  cudaEventDisableTiming);
        cudaEventCreateWithFlags(&evX2,  cudaEventDisableTiming);
        cudaEventCreateWithFlags(&evX3,  cudaEventDisableTiming);
        cudaEventCreateWithFlags(&evR0,  cudaEventDisableTiming);
        cudaEventCreateWithFlags(&evR1,  cudaEventDisableTiming);
        cudaEventCreateWithFlags(&evR2,  cudaEventDisableTiming);
        cudaEventCreateWithFlags(&evOut, cudaEventDisableTiming);
    }

    // prep + xp0 serial on main
    prep_split<<<32, 256>>>(Wx, Wy);
    xp_tensor<<<dim3(16, NB), 256>>>(x, 0);
    cudaEventRecord(ev0, 0);

    // xp1..xp3 on s1
    cudaStreamWaitEvent(s1, ev0, 0);
    xp_tensor<<<dim3(16, NB), 256, 0, s1>>>(x, 1024);
    cudaEventRecord(evX1, s1);
    xp_tensor<<<dim3(16, NB), 256, 0, s1>>>(x, 2048);
    cudaEventRecord(evX2, s1);
    xp_tensor<<<dim3(16, NB), 256, 0, s1>>>(x, 3072);
    cudaEventRecord(evX3, s1);

    // rec chain on main, gated by xp events
    rnn_rec_chunk<<<NB / 2, 256>>>(Wh, bh, bx, 0, 1024);
    cudaEventRecord(evR0, 0);
    cudaStreamWaitEvent(0, evX1, 0);
    rnn_rec_chunk<<<NB / 2, 256>>>(Wh, bh, bx, 1024, 2048);
    cudaEventRecord(evR1, 0);
    cudaStreamWaitEvent(0, evX2, 0);
    rnn_rec_chunk<<<NB / 2, 256>>>(Wh, bh, bx, 2048, 3072);
    cudaEventRecord(evR2, 0);
    cudaStreamWaitEvent(0, evX3, 0);
    rnn_rec_chunk<<<NB / 2, 256>>>(Wh, bh, bx, 3072, 4096);

    // out0..out2 on s1, gated by rec events
    cudaStreamWaitEvent(s1, evR0, 0);
    out_tensor<<<dim3(32, NB), 256, 0, s1>>>(by, out, 0);
    cudaStreamWaitEvent(s1, evR1, 0);
    out_tensor<<<dim3(32, NB), 256, 0, s1>>>(by, out, 1024);
    cudaStreamWaitEvent(s1, evR2, 0);
    out_tensor<<<dim3(32, NB), 256, 0, s1>>>(by, out, 2048);
    cudaEventRecord(evOut, s1);

    // join + out3 on main
    cudaStreamWaitEvent(0, evOut, 0);
    out_tensor<<<dim3(32, NB), 256>>>(by, out, 3072);
}